// round 9
// baseline (speedup 1.0000x reference)
#include <cuda_runtime.h>
#include <cuda_bf16.h>
#include <cstdint>

#define EPS  1e-6f
#define BB   512
#define KK   1024
#define DDIM 256

// ---------------- scratch (device globals: allocation-free) -----------------
__device__ __nv_bfloat16 g_xh[BB * DDIM], g_xl[BB * DDIM];
__device__ __nv_bfloat16 g_ph[KK * DDIM], g_pl[KK * DDIM];
__device__ __nv_bfloat16 g_ah[KK * DDIM], g_al[KK * DDIM];
__device__ float g_x2[BB], g_p2[KK], g_pa[KK], g_na2[KK];

// ---------------- helpers ----------------------------------------------------
__device__ __forceinline__ uint32_t smem_u32(const void* p) {
    uint32_t r;
    asm("{ .reg .u64 t; cvta.to.shared.u64 t, %1; cvt.u32.u64 %0, t; }"
        : "=r"(r) : "l"(p));
    return r;
}
__device__ __forceinline__ void ldsm_x4(uint32_t* r, uint32_t addr) {
    asm volatile("ldmatrix.sync.aligned.m8n8.x4.shared.b16 {%0,%1,%2,%3}, [%4];"
                 : "=r"(r[0]), "=r"(r[1]), "=r"(r[2]), "=r"(r[3]) : "r"(addr));
}
__device__ __forceinline__ void mma_bf16(float* d, const uint32_t* a,
                                         uint32_t b0, uint32_t b1) {
    asm volatile(
        "mma.sync.aligned.m16n8k16.row.col.f32.bf16.bf16.f32 "
        "{%0,%1,%2,%3}, {%4,%5,%6,%7}, {%8,%9}, {%0,%1,%2,%3};"
        : "+f"(d[0]), "+f"(d[1]), "+f"(d[2]), "+f"(d[3])
        : "r"(a[0]), "r"(a[1]), "r"(a[2]), "r"(a[3]), "r"(b0), "r"(b1));
}
__device__ __forceinline__ void cp16(uint32_t dst, const void* src) {
    asm volatile("cp.async.cg.shared.global [%0], [%1], 16;"
                 :: "r"(dst), "l"(src) : "memory");
}
#define CP_COMMIT() asm volatile("cp.async.commit_group;" ::: "memory")
#define CP_WAIT(n)  asm volatile("cp.async.wait_group %0;" :: "n"(n) : "memory")

// ============================================================================
// Kernel 1: fp32 -> bf16 hi/lo splits + exact fp32 stats. One warp per row.
// ============================================================================
__device__ __forceinline__ uint32_t pack_hi(float f0, float f1,
                                            float& r0, float& r1) {
    __nv_bfloat16 h0 = __float2bfloat16_rn(f0);
    __nv_bfloat16 h1 = __float2bfloat16_rn(f1);
    r0 = f0 - __bfloat162float(h0);
    r1 = f1 - __bfloat162float(h1);
    return (uint32_t)__bfloat16_as_ushort(h0) |
           ((uint32_t)__bfloat16_as_ushort(h1) << 16);
}
__device__ __forceinline__ uint32_t pack_lo(float r0, float r1) {
    return (uint32_t)__bfloat16_as_ushort(__float2bfloat16_rn(r0)) |
           ((uint32_t)__bfloat16_as_ushort(__float2bfloat16_rn(r1)) << 16);
}
__device__ __forceinline__ void split8(const float* f, uint4& hi, uint4& lo) {
    float r[8];
    hi.x = pack_hi(f[0], f[1], r[0], r[1]);
    hi.y = pack_hi(f[2], f[3], r[2], r[3]);
    hi.z = pack_hi(f[4], f[5], r[4], r[5]);
    hi.w = pack_hi(f[6], f[7], r[6], r[7]);
    lo.x = pack_lo(r[0], r[1]); lo.y = pack_lo(r[2], r[3]);
    lo.z = pack_lo(r[4], r[5]); lo.w = pack_lo(r[6], r[7]);
}

__global__ __launch_bounds__(256)
void conv_stats_kernel(const float* __restrict__ x,
                       const float* __restrict__ p,
                       const float* __restrict__ a)
{
    const int w    = blockIdx.x * 8 + (threadIdx.x >> 5);
    const int lane = threadIdx.x & 31;
    if (w < BB) {
        const int r = w;
        float f[8];
        *(float4*)&f[0] = *(const float4*)(x + r * DDIM + lane * 8);
        *(float4*)&f[4] = *(const float4*)(x + r * DDIM + lane * 8 + 4);
        uint4 hi, lo;
        split8(f, hi, lo);
        *(uint4*)(g_xh + r * DDIM + lane * 8) = hi;
        *(uint4*)(g_xl + r * DDIM + lane * 8) = lo;
        float x2 = 0.f;
        #pragma unroll
        for (int i = 0; i < 8; i++) x2 += f[i] * f[i];
        #pragma unroll
        for (int m = 16; m; m >>= 1) x2 += __shfl_xor_sync(~0u, x2, m);
        if (lane == 0) g_x2[r] = x2;
    } else {
        const int r = w - BB;
        float fp[8], fa[8];
        *(float4*)&fp[0] = *(const float4*)(p + r * DDIM + lane * 8);
        *(float4*)&fp[4] = *(const float4*)(p + r * DDIM + lane * 8 + 4);
        *(float4*)&fa[0] = *(const float4*)(a + r * DDIM + lane * 8);
        *(float4*)&fa[4] = *(const float4*)(a + r * DDIM + lane * 8 + 4);
        uint4 hi, lo;
        split8(fp, hi, lo);
        *(uint4*)(g_ph + r * DDIM + lane * 8) = hi;
        *(uint4*)(g_pl + r * DDIM + lane * 8) = lo;
        split8(fa, hi, lo);
        *(uint4*)(g_ah + r * DDIM + lane * 8) = hi;
        *(uint4*)(g_al + r * DDIM + lane * 8) = lo;
        float p2 = 0.f, pa = 0.f, na2 = 0.f;
        #pragma unroll
        for (int i = 0; i < 8; i++) {
            p2 += fp[i] * fp[i]; pa += fp[i] * fa[i]; na2 += fa[i] * fa[i];
        }
        #pragma unroll
        for (int m = 16; m; m >>= 1) {
            p2  += __shfl_xor_sync(~0u, p2,  m);
            pa  += __shfl_xor_sync(~0u, pa,  m);
            na2 += __shfl_xor_sync(~0u, na2, m);
        }
        if (lane == 0) { g_p2[r] = p2; g_pa[r] = pa; g_na2[r] = na2; }
    }
}

// ============================================================================
// Kernel 2: dual split-GEMM (mma.sync bf16), 3-stage cp.async, 1 sync/chunk.
//   CTA: 64(m) x 32(n), 8 warps 4x2, warp tile 16x16. 2 CTAs/SM.
//   Stage = 16KB; 3 stages = 49152B (exactly the no-opt-in smem limit).
//   Per-kstep accumulators + term-major MMA order -> 8 independent chains.
// ============================================================================
#define MT    64
#define NT    32
#define KC    32
#define NCH   (DDIM / KC)   // 8
#define STAGE 16384
#define XOFF  0
#define POFF  8192
#define AOFF  12288
#define SMEM2 (3 * STAGE)   // 49152

__global__ __launch_bounds__(256, 2)
void hyp_hmma_kernel(float* __restrict__ out)
{
    extern __shared__ char smem[];
    const uint32_t smb = smem_u32(smem);

    const int tid  = threadIdx.x;
    const int wid  = tid >> 5;
    const int lane = tid & 31;
    const int k0   = blockIdx.x * NT;
    const int b0   = blockIdx.y * MT;

    // ---- cp.async loader: 4x 16B per thread per chunk -----------------------
    const int xrow = tid >> 2, xseg = tid & 3;                 // X: 64 rows
    const int phalf = tid >> 7;                                // P/A hi or lo
    const int prow = (tid & 127) >> 2, pseg = tid & 3;         // 32 rows
    const __nv_bfloat16* xsrc_h = g_xh + (size_t)(b0 + xrow) * DDIM + xseg * 8;
    const __nv_bfloat16* xsrc_l = g_xl + (size_t)(b0 + xrow) * DDIM + xseg * 8;
    const __nv_bfloat16* psrc = (phalf ? g_pl : g_ph) + (size_t)(k0 + prow) * DDIM + pseg * 8;
    const __nv_bfloat16* asrc = (phalf ? g_al : g_ah) + (size_t)(k0 + prow) * DDIM + pseg * 8;
    const uint32_t xdst_h = XOFF + xrow * 128 + ((xseg * 16)      ^ ((xrow & 7) << 4));
    const uint32_t xdst_l = XOFF + xrow * 128 + ((64 + xseg * 16) ^ ((xrow & 7) << 4));
    const uint32_t pdst   = POFF + prow * 128 + ((phalf * 64 + pseg * 16) ^ ((prow & 7) << 4));
    const uint32_t adst   = pdst + (AOFF - POFF);

    auto load_chunk = [&](int stage, int c) {
        const int c0 = c * KC;
        const uint32_t sb = smb + stage * STAGE;
        cp16(sb + xdst_h, xsrc_h + c0);
        cp16(sb + xdst_l, xsrc_l + c0);
        cp16(sb + pdst,   psrc + c0);
        cp16(sb + adst,   asrc + c0);
        CP_COMMIT();
    };

    // ---- warp tiling / ldsm addressing --------------------------------------
    const int wm = (wid >> 1) * 16;          // warp m offset (4 warps)
    const int wn = (wid & 1)  * 16;          // warp n offset (2 warps)
    const int g  = lane >> 3;
    const int r  = lane & 7;
    const int rowadd = (g & 1) * 8 + r;      // 0..15
    const int cadd   = ((g >> 1) * 8) * 2;   // 0 or 16 bytes
    const uint32_t rxor  = (rowadd & 7) << 4;
    const uint32_t xterm = XOFF + (wm + rowadd) * 128;
    const uint32_t pterm = POFF + (wn + rowadd) * 128;
    const uint32_t aterm = AOFF + (wn + rowadd) * 128;
    // precomputed ldsm column offsets: [ks][hi/lo]
    const uint32_t off_h[2] = { (0u  + cadd) ^ rxor, (32u + cadd) ^ rxor };
    const uint32_t off_l[2] = { (64u + cadd) ^ rxor, (96u + cadd) ^ rxor };

    // per-kstep accumulators: 8 independent dependency chains
    float accP[2][2][4] = {}, accA[2][2][4] = {};

    load_chunk(0, 0);
    load_chunk(1, 1);

    for (int c = 0; c < NCH; c++) {
        if (c < NCH - 1) CP_WAIT(1); else CP_WAIT(0);
        __syncthreads();   // stage (c+2)%3 free for refill; chunk c visible

        if (c + 2 < NCH) load_chunk((c + 2) % 3, c + 2);

        const uint32_t sb = smb + (c % 3) * STAGE;
        uint32_t axh[2][4], axl[2][4], bph[2][4], bpl[2][4], bah[2][4], bal[2][4];
        #pragma unroll
        for (int ks = 0; ks < 2; ks++) {
            ldsm_x4(axh[ks], sb + xterm + off_h[ks]);
            ldsm_x4(axl[ks], sb + xterm + off_l[ks]);
            ldsm_x4(bph[ks], sb + pterm + off_h[ks]);
            ldsm_x4(bpl[ks], sb + pterm + off_l[ks]);
            ldsm_x4(bah[ks], sb + aterm + off_h[ks]);
            ldsm_x4(bal[ks], sb + aterm + off_l[ks]);
        }
        // term 1: hi*hi  (8 independent MMAs)
        #pragma unroll
        for (int ks = 0; ks < 2; ks++)
            #pragma unroll
            for (int n = 0; n < 2; n++) {
                mma_bf16(accP[ks][n], axh[ks], bph[ks][n], bph[ks][n + 2]);
                mma_bf16(accA[ks][n], axh[ks], bah[ks][n], bah[ks][n + 2]);
            }
        // term 2: lo*hi
        #pragma unroll
        for (int ks = 0; ks < 2; ks++)
            #pragma unroll
            for (int n = 0; n < 2; n++) {
                mma_bf16(accP[ks][n], axl[ks], bph[ks][n], bph[ks][n + 2]);
                mma_bf16(accA[ks][n], axl[ks], bah[ks][n], bah[ks][n + 2]);
            }
        // term 3: hi*lo  (ll term dropped, ~2^-16 rel)
        #pragma unroll
        for (int ks = 0; ks < 2; ks++)
            #pragma unroll
            for (int n = 0; n < 2; n++) {
                mma_bf16(accP[ks][n], axh[ks], bpl[ks][n], bpl[ks][n + 2]);
                mma_bf16(accA[ks][n], axh[ks], bal[ks][n], bal[ks][n + 2]);
            }
    }

    // ---- epilogue: merge ksteps + hyperbolic MLR logit (stats from L2) ------
    #pragma unroll
    for (int h = 0; h < 2; h++) {
        const int mloc = wm + h * 8 + (lane >> 2);
        const float x2 = g_x2[b0 + mloc];
        #pragma unroll
        for (int n = 0; n < 2; n++) {
            const int kloc = wn + n * 8 + (lane & 3) * 2;
            float2 res;
            float* rr = (float*)&res;
            #pragma unroll
            for (int q = 0; q < 2; q++) {
                const int kc2 = kloc + q;
                const float xp  = accP[0][n][h * 2 + q] + accP[1][n][h * 2 + q];
                const float xa  = accA[0][n][h * 2 + q] + accA[1][n][h * 2 + q];
                const float p2  = g_p2[k0 + kc2];
                const float pa  = g_pa[k0 + kc2];
                const float na2 = g_na2[k0 + kc2];

                float beta  = 1.f - p2;
                float alpha = -(1.f - 2.f * xp + x2);
                float den   = 1.f - 2.f * xp + p2 * x2 + EPS;
                float inv   = 1.f / den;
                float z2 = (alpha*alpha*p2 + 2.f*alpha*beta*xp + beta*beta*x2)
                           * inv * inv;
                float za = beta * (alpha * pa + beta * xa) * inv;
                float na = beta * sqrtf(na2);
                float lam = 2.f / (beta + EPS);
                float tt = 2.f * za / ((1.f - z2) * na + EPS);
                rr[q] = lam * na * asinhf(tt);
            }
            *(float2*)(out + (size_t)(b0 + mloc) * KK + k0 + kloc) = res;
        }
    }
}

// ============================================================================
extern "C" void kernel_launch(void* const* d_in, const int* in_sizes, int n_in,
                              void* d_out, int out_size)
{
    const float* x = (const float*)d_in[0];
    const float* p = (const float*)d_in[1];
    const float* a = (const float*)d_in[2];
    float* out = (float*)d_out;

    conv_stats_kernel<<<(BB + KK) / 8, 256>>>(x, p, a);

    dim3 grid(KK / NT, BB / MT);    // (32, 8) = 256 CTAs, 2/SM, one wave
    hyp_hmma_kernel<<<grid, 256, SMEM2>>>(out);   // 48KB dynamic smem exactly
}